// round 11
// baseline (speedup 1.0000x reference)
#include <cuda_runtime.h>
#include <cstdint>
#include <math.h>

#define H 128
#define MAXB 8192
#define RPB 8   // rows per MLP block

__device__ float g_sent[(size_t)MAXB * H];   // zero-init; re-zeroed each call
__device__ int   g_cnt[MAXB];                // zero-init; re-zeroed each call

#define CP_ASYNC_CG(dst_u32, src_ptr) \
    asm volatile("cp.async.cg.shared.global [%0], [%1], 16;" :: "r"(dst_u32), "l"(src_ptr))
#define CP_COMMIT() asm volatile("cp.async.commit_group;")
#define CP_WAIT1()  asm volatile("cp.async.wait_group 1;" ::: "memory")

// ---------------------------------------------------------------------------
// Kernel 1: token-chunk gather. Block = 128 contiguous tokens (balanced).
// Warp w owns contiguous rows [32w, 32w+32) of the chunk; cp.async double
// buffering (warp-private, no mainloop barriers). Sorted segment_ids =>
// each warp crosses at most a couple of boundaries; per-segment accumulators
// are flushed to g_sent/g_cnt with atomics at boundaries.
// ---------------------------------------------------------------------------
__global__ __launch_bounds__(128) void gather_kernel(
    const int*   __restrict__ token_ids,
    const int*   __restrict__ seg_ids,
    const float* __restrict__ embed,
    float*       __restrict__ out,
    int T)
{
    const int chunk0 = blockIdx.x * 128;
    const int tid = threadIdx.x;
    const int w   = tid >> 5;
    const int l   = tid & 31;

    if (blockIdx.x == 0 && tid == 0) *out = 0.0f;   // harness poisons d_out

    const int n = min(128, T - chunk0);

    __shared__ int s_tok[128];
    __shared__ int s_seg[128];
    __shared__ __align__(16) float4 s_buf[4][2][4][32];  // [warp][slot][row][lane]

    if (tid < n) {
        s_tok[tid] = token_ids[chunk0 + tid];
        s_seg[tid] = seg_ids[chunk0 + tid];
    }
    __syncthreads();

    const int rlo = 32 * w;
    const int rhi = min(n, rlo + 32);
    const int ngroups = (rhi > rlo) ? ((rhi - rlo + 3) >> 2) : 0;

    const unsigned int sbase =
        (unsigned int)__cvta_generic_to_shared(&s_buf[w][0][0][l]);
    const char* E = (const char*)embed;

    float4 acc0 = make_float4(0.f, 0.f, 0.f, 0.f), acc1 = acc0;
    int cur = (rhi > rlo) ? s_seg[rlo] : -1;
    int cnt = 0;

#define FLUSH(s)                                                           \
    do {                                                                   \
        float* _dst = &g_sent[(size_t)(s) * H + 4 * l];                    \
        atomicAdd(_dst + 0, acc0.x + acc1.x);                              \
        atomicAdd(_dst + 1, acc0.y + acc1.y);                              \
        atomicAdd(_dst + 2, acc0.z + acc1.z);                              \
        atomicAdd(_dst + 3, acc0.w + acc1.w);                              \
        if (l == 0) atomicAdd(&g_cnt[s], cnt);                             \
        acc0 = make_float4(0.f, 0.f, 0.f, 0.f); acc1 = acc0; cnt = 0;      \
    } while (0)

#define FILL(g)                                                            \
    do {                                                                   \
        const int _g = (g);                                                \
        if (_g < ngroups) {                                                \
            const int _r0 = rlo + _g * 4;                                  \
            _Pragma("unroll")                                              \
            for (int _j = 0; _j < 4; _j++) {                               \
                const int _r = _r0 + _j;                                   \
                if (_r < rhi) {                                            \
                    const int _tok = s_tok[_r];                            \
                    CP_ASYNC_CG(sbase + (unsigned int)((_g & 1) * 2048 + _j * 512), \
                                E + (size_t)_tok * 512 + l * 16);          \
                }                                                          \
            }                                                              \
        }                                                                  \
        CP_COMMIT();                                                       \
    } while (0)

    FILL(0);
    FILL(1);

    for (int g = 0; g < ngroups; g++) {
        CP_WAIT1();
        const int r0   = rlo + 4 * g;
        const int slot = g & 1;
#pragma unroll
        for (int j = 0; j < 4; j++) {
            const int r = r0 + j;
            if (r < rhi) {
                const int s = s_seg[r];             // broadcast LDS
                if (s != cur) { FLUSH(cur); cur = s; }
                const float4 v = s_buf[w][slot][j][l];
                if (j & 1) { acc1.x += v.x; acc1.y += v.y;
                             acc1.z += v.z; acc1.w += v.w; }
                else       { acc0.x += v.x; acc0.y += v.y;
                             acc0.z += v.z; acc0.w += v.w; }
                cnt++;
            }
        }
        FILL(g + 2);
    }

    if (cur >= 0 && cnt > 0) FLUSH(cur);
#undef FILL
#undef FLUSH
}

// ---------------------------------------------------------------------------
// Kernel 2: mean + MLP head + BCE. 8 rows per 256-thread block, k-split
// halves. After staging, re-zeroes its g_sent/g_cnt rows so every
// kernel_launch starts from clean scratch (graph-replay safe).
// ---------------------------------------------------------------------------
__global__ __launch_bounds__(256) void mlp_bce_kernel(
    const float* __restrict__ y_true,
    const float* __restrict__ W_hid,   // [H,H] row-major
    const float* __restrict__ b_hid,
    const float* __restrict__ W_out,
    const float* __restrict__ b_out,
    float*       __restrict__ out,
    int B)
{
    const int t    = threadIdx.x;
    const int row0 = blockIdx.x * RPB;
    const int kh   = t >> 7;           // k-half
    const int col  = t & 127;

    __shared__ float s_t[H][RPB];      // transposed mean tile
    __shared__ float s_p[2][RPB][H];   // per-half partials
    __shared__ float red[RPB][4];
    __shared__ float s_inv[RPB];

    if (t < RPB) {
        const int row = row0 + t;
        const int c = (row < B) ? g_cnt[row] : 0;
        s_inv[t] = 1.0f / (float)max(c, 1);
    }
    __syncthreads();

    for (int e = t; e < RPB * H; e += 256) {
        const int r = e >> 7;
        const int k = e & 127;
        const int row = row0 + r;
        s_t[k][r] = (row < B) ? g_sent[(size_t)row * H + k] * s_inv[r] : 0.f;
    }
    __syncthreads();

    // cleanup for the next graph replay (rows now safely staged in s_t)
    for (int e = t; e < RPB * H; e += 256) {
        const int r = e >> 7;
        const int k = e & 127;
        const int row = row0 + r;
        if (row < B) g_sent[(size_t)row * H + k] = 0.f;
    }
    if (t < RPB && row0 + t < B) g_cnt[row0 + t] = 0;

    float acc[RPB];
#pragma unroll
    for (int r = 0; r < RPB; r++) acc[r] = 0.f;

    const int k0 = kh * 64;
#pragma unroll 4
    for (int kk = 0; kk < 64; kk++) {
        const int k = k0 + kk;
        const float  wv = __ldg(&W_hid[k * H + col]);
        const float4 sa = *(const float4*)&s_t[k][0];
        const float4 sb = *(const float4*)&s_t[k][4];
        acc[0] += sa.x * wv;  acc[1] += sa.y * wv;
        acc[2] += sa.z * wv;  acc[3] += sa.w * wv;
        acc[4] += sb.x * wv;  acc[5] += sb.y * wv;
        acc[6] += sb.z * wv;  acc[7] += sb.w * wv;
    }
#pragma unroll
    for (int r = 0; r < RPB; r++) s_p[kh][r][col] = acc[r];
    __syncthreads();

    if (t < 128) {
        const float bh = b_hid[col];
        const float wo = W_out[col];
        float val[RPB];
#pragma unroll
        for (int r = 0; r < RPB; r++)
            val[r] = tanhf(s_p[0][r][col] + s_p[1][r][col] + bh) * wo;

#pragma unroll
        for (int off = 16; off > 0; off >>= 1)
#pragma unroll
            for (int r = 0; r < RPB; r++)
                val[r] += __shfl_xor_sync(0xffffffffu, val[r], off);

        if ((t & 31) == 0)
#pragma unroll
            for (int r = 0; r < RPB; r++) red[r][t >> 5] = val[r];
    }
    __syncthreads();

    if (t < RPB) {
        const int row = row0 + t;
        float loss = 0.f;
        if (row < B) {
            const float z = (red[t][0] + red[t][1]) +
                            (red[t][2] + red[t][3]) + __ldg(b_out);
            const float lp  = fmaxf(-log1pf(expf(-z)), -100.0f);
            const float l1m = fmaxf(-log1pf(expf(z)),  -100.0f);
            const float y   = __ldg(&y_true[row]);
            loss = -(y * lp + (1.0f - y) * l1m);
        }
#pragma unroll
        for (int off = 4; off > 0; off >>= 1)
            loss += __shfl_xor_sync(0x000000ffu, loss, off);
        if (t == 0) atomicAdd(out, loss);
    }
}

// ---------------------------------------------------------------------------
extern "C" void kernel_launch(void* const* d_in, const int* in_sizes, int n_in,
                              void* d_out, int out_size)
{
    const int*   token_ids = (const int*)d_in[0];
    const int*   seg_ids   = (const int*)d_in[1];
    const float* y_true    = (const float*)d_in[2];
    const float* embed     = (const float*)d_in[3];
    const float* W_hid     = (const float*)d_in[4];
    const float* b_hid     = (const float*)d_in[5];
    const float* W_out     = (const float*)d_in[6];
    const float* b_out     = (const float*)d_in[7];

    const int T = in_sizes[0];
    const int B = in_sizes[2];
    float* out = (float*)d_out;

    gather_kernel<<<(T + 127) / 128, 128>>>(token_ids, seg_ids, embed, out, T);

    mlp_bce_kernel<<<(B + RPB - 1) / RPB, 256>>>(y_true, W_hid, b_hid,
                                                 W_out, b_out, out, B);
}

// round 12
// speedup vs baseline: 1.0793x; 1.0793x over previous
#include <cuda_runtime.h>
#include <cstdint>
#include <math.h>

#define H 128
#define MAXB 8192
#define RPB 8   // rows per MLP block

__device__ int   g_starts[MAXB + 1];
__device__ float g_sent[(size_t)MAXB * H];

#define CP_ASYNC_CG(dst_u32, src_ptr) \
    asm volatile("cp.async.cg.shared.global [%0], [%1], 16;" :: "r"(dst_u32), "l"(src_ptr))
#define CP_COMMIT() asm volatile("cp.async.commit_group;")
#define CP_WAIT1()  asm volatile("cp.async.wait_group 1;" ::: "memory")

// ---------------------------------------------------------------------------
// Kernel 0: prepass (R9-proven). 4 tokens/thread via int4; builds g_starts
// from sorted segment_ids and zeroes the output scalar.
// ---------------------------------------------------------------------------
__global__ __launch_bounds__(256) void prepass_kernel(
    const int* __restrict__ seg_ids, float* __restrict__ out, int T, int B)
{
    const int gid = blockIdx.x * blockDim.x + threadIdx.x;
    if (gid == 0) *out = 0.0f;

    const int i0 = gid * 4;
    if (i0 >= T) return;

    int v[4];
    if (i0 + 3 < T) {
        const int4 q = __ldg(&((const int4*)seg_ids)[gid]);
        v[0] = q.x; v[1] = q.y; v[2] = q.z; v[3] = q.w;
    } else {
        for (int j = 0; j < 4; j++)
            v[j] = (i0 + j < T) ? __ldg(&seg_ids[i0 + j]) : v[j > 0 ? j - 1 : 0];
    }

    int prev = (i0 == 0) ? -1 : __ldg(&seg_ids[i0 - 1]);
#pragma unroll
    for (int j = 0; j < 4; j++) {
        const int i = i0 + j;
        if (i >= T) break;
        const int cur = v[j];
        for (int s = prev + 1; s <= cur; s++) g_starts[s] = i;
        if (i == T - 1)
            for (int s = cur + 1; s <= B; s++) g_starts[s] = T;
        prev = cur;
    }
}

// ---------------------------------------------------------------------------
// Kernel 1: gather + segment mean via cp.async double-buffering (R9-proven).
// One CTA per segment; warp-private pipeline, no mainloop barriers.
// ---------------------------------------------------------------------------
__global__ __launch_bounds__(128) void seg_mean_kernel(
    const int*   __restrict__ token_ids,
    const float* __restrict__ embed)
{
    const int seg = blockIdx.x;
    const int tid = threadIdx.x;
    const int w   = tid >> 5;
    const int l   = tid & 31;

    const int start = __ldg(&g_starts[seg]);
    const int end   = __ldg(&g_starts[seg + 1]);
    const int n     = end - start;
    const int chunks = (n + 15) >> 4;

    __shared__ __align__(16) float4 s_buf[4][2][4][32];  // [warp][slot][row][lane]
    __shared__ float s_part[4][H];

    const unsigned int sbase =
        (unsigned int)__cvta_generic_to_shared(&s_buf[w][0][0][l]);
    const char* E = (const char*)embed;

    float4 a0 = make_float4(0.f, 0.f, 0.f, 0.f), a1 = a0;

#define FILL(c)                                                            \
    do {                                                                   \
        const int _c = (c);                                                \
        if (_c < chunks) {                                                 \
            const int _base = start + _c * 16 + w * 4;                     \
            _Pragma("unroll")                                              \
            for (int _j = 0; _j < 4; _j++) {                               \
                const int _idx = _base + _j;                               \
                if (_idx < end) {                                          \
                    const int _tok = __ldg(&token_ids[_idx]);              \
                    CP_ASYNC_CG(sbase + (unsigned int)((_c & 1) * 2048 + _j * 512), \
                                E + (size_t)_tok * 512 + l * 16);          \
                }                                                          \
            }                                                              \
        }                                                                  \
        CP_COMMIT();                                                       \
    } while (0)

    FILL(0);
    FILL(1);

    for (int c = 0; c < chunks; c++) {
        CP_WAIT1();
        const int base = c * 16 + w * 4;
        const int m    = n - base;
        const int slot = c & 1;
        if (m >= 1) { const float4 v = s_buf[w][slot][0][l];
                      a0.x += v.x; a0.y += v.y; a0.z += v.z; a0.w += v.w; }
        if (m >= 2) { const float4 v = s_buf[w][slot][1][l];
                      a1.x += v.x; a1.y += v.y; a1.z += v.z; a1.w += v.w; }
        if (m >= 3) { const float4 v = s_buf[w][slot][2][l];
                      a0.x += v.x; a0.y += v.y; a0.z += v.z; a0.w += v.w; }
        if (m >= 4) { const float4 v = s_buf[w][slot][3][l];
                      a1.x += v.x; a1.y += v.y; a1.z += v.z; a1.w += v.w; }
        FILL(c + 2);
    }
#undef FILL

    float4 asum;
    asum.x = a0.x + a1.x;  asum.y = a0.y + a1.y;
    asum.z = a0.z + a1.z;  asum.w = a0.w + a1.w;
    *(float4*)&s_part[w][4 * l] = asum;
    __syncthreads();

    const float inv = 1.0f / (float)max(n, 1);
    g_sent[(size_t)seg * H + tid] =
        ((s_part[0][tid] + s_part[1][tid]) +
         (s_part[2][tid] + s_part[3][tid])) * inv;
}

// ---------------------------------------------------------------------------
// Kernel 2: MLP head + BCE. 8 rows per 512-thread block, 4-way k-split
// (quarter q covers k in [32q, 32q+32)) -> grid 512 x 16 warps = ~87%
// achievable occupancy at 3.5 blocks/SM, mainloop only 32 iterations,
// W traffic unchanged (32MB, L2-hot).
// ---------------------------------------------------------------------------
__global__ __launch_bounds__(512) void mlp_bce_kernel(
    const float* __restrict__ y_true,
    const float* __restrict__ W_hid,   // [H,H] row-major
    const float* __restrict__ b_hid,
    const float* __restrict__ W_out,
    const float* __restrict__ b_out,
    float*       __restrict__ out,
    int B)
{
    const int t    = threadIdx.x;
    const int row0 = blockIdx.x * RPB;
    const int kq   = t >> 7;           // k-quarter 0..3
    const int col  = t & 127;

    __shared__ float s_t[H][RPB];      // transposed sentence tile (4KB)
    __shared__ float s_p[4][RPB][H];   // per-quarter partials (16KB)
    __shared__ float red[RPB][4];

#pragma unroll
    for (int e = t; e < RPB * H; e += 512) {
        const int r = e >> 7;
        const int k = e & 127;
        const int row = min(row0 + r, B - 1);
        s_t[k][r] = g_sent[(size_t)row * H + k];
    }
    __syncthreads();

    float acc[RPB];
#pragma unroll
    for (int r = 0; r < RPB; r++) acc[r] = 0.f;

    const int k0 = kq * 32;
#pragma unroll 4
    for (int kk = 0; kk < 32; kk++) {
        const int k = k0 + kk;
        const float  wv = __ldg(&W_hid[k * H + col]);
        const float4 sa = *(const float4*)&s_t[k][0];   // broadcast LDS.128
        const float4 sb = *(const float4*)&s_t[k][4];
        acc[0] += sa.x * wv;  acc[1] += sa.y * wv;
        acc[2] += sa.z * wv;  acc[3] += sa.w * wv;
        acc[4] += sb.x * wv;  acc[5] += sb.y * wv;
        acc[6] += sb.z * wv;  acc[7] += sb.w * wv;
    }
#pragma unroll
    for (int r = 0; r < RPB; r++) s_p[kq][r][col] = acc[r];
    __syncthreads();

    if (t < 128) {                      // 4 warps finish up
        const float bh = b_hid[col];
        const float wo = W_out[col];
        float val[RPB];
#pragma unroll
        for (int r = 0; r < RPB; r++)
            val[r] = tanhf((s_p[0][r][col] + s_p[1][r][col]) +
                           (s_p[2][r][col] + s_p[3][r][col]) + bh) * wo;

#pragma unroll
        for (int off = 16; off > 0; off >>= 1)
#pragma unroll
            for (int r = 0; r < RPB; r++)
                val[r] += __shfl_xor_sync(0xffffffffu, val[r], off);

        if ((t & 31) == 0)
#pragma unroll
            for (int r = 0; r < RPB; r++) red[r][t >> 5] = val[r];
    }
    __syncthreads();

    if (t < RPB) {
        const int row = row0 + t;
        float loss = 0.f;
        if (row < B) {
            const float z = (red[t][0] + red[t][1]) +
                            (red[t][2] + red[t][3]) + __ldg(b_out);
            const float lp  = fmaxf(-log1pf(expf(-z)), -100.0f);
            const float l1m = fmaxf(-log1pf(expf(z)),  -100.0f);
            const float y   = __ldg(&y_true[row]);
            loss = -(y * lp + (1.0f - y) * l1m);
        }
#pragma unroll
        for (int off = 4; off > 0; off >>= 1)
            loss += __shfl_xor_sync(0x000000ffu, loss, off);
        if (t == 0) atomicAdd(out, loss);
    }
}

// ---------------------------------------------------------------------------
extern "C" void kernel_launch(void* const* d_in, const int* in_sizes, int n_in,
                              void* d_out, int out_size)
{
    const int*   token_ids = (const int*)d_in[0];
    const int*   seg_ids   = (const int*)d_in[1];
    const float* y_true    = (const float*)d_in[2];
    const float* embed     = (const float*)d_in[3];
    const float* W_hid     = (const float*)d_in[4];
    const float* b_hid     = (const float*)d_in[5];
    const float* W_out     = (const float*)d_in[6];
    const float* b_out     = (const float*)d_in[7];

    const int T = in_sizes[0];
    const int B = in_sizes[2];
    float* out = (float*)d_out;

    const int vthreads = (T + 3) / 4;
    prepass_kernel<<<(vthreads + 255) / 256, 256>>>(seg_ids, out, T, B);

    seg_mean_kernel<<<B, 128>>>(token_ids, embed);

    mlp_bce_kernel<<<(B + RPB - 1) / RPB, 512>>>(y_true, W_hid, b_hid,
                                                 W_out, b_out, out, B);
}